// round 1
// baseline (speedup 1.0000x reference)
#include <cuda_runtime.h>

// ---------------------------------------------------------------------------
// SNN ResNet forward, 8 timesteps, B=32. fp32 direct convolutions with fused
// LIF (leaky integrate-and-fire, soft reset), dropout masks, residual adds.
// ---------------------------------------------------------------------------

#define B 32
#define TSTEPS 8

// membrane state offsets (floats) in one big device array
#define OFF_M0  0u          // 32*64*32*32 = 2097152
#define OFF_M1  2097152u
#define OFF_M2  4194304u
#define OFF_M3  6291456u    // 32*64*16*16 = 524288
#define OFF_M4  6815744u
#define OFF_M5  7340032u    // 32*128*8*8 = 262144
#define OFF_M6  7602176u
#define OFF_M7  7864320u    // 32*256*4*4 = 131072
#define OFF_M8  7995392u
#define OFF_M9  8126464u    // 32*512*2*2 = 65536
#define OFF_M10 8192000u
#define MEM_TOTAL 8257536u

__device__ float g_mem[MEM_TOTAL];
__device__ float g_A[2097152];
__device__ float g_B[2097152];
__device__ float g_C[2097152];

__global__ void zero_kernel(float* __restrict__ p, int n) {
    int i = blockIdx.x * blockDim.x + threadIdx.x;
    if (i < n) p[i] = 0.0f;
}

// 3x3 conv (pad=1) + optional residual + LIF + optional dropout mask.
// Each thread computes 4 consecutive outputs along W (register tiling).
template <int STRIDE>
__global__ __launch_bounds__(256)
void conv3x3_lif(const float* __restrict__ in, const float* __restrict__ wgt,
                 const float* __restrict__ res, const float* __restrict__ mask,
                 float* __restrict__ mem, float* __restrict__ out,
                 const float* __restrict__ thr_a, const float* __restrict__ leak_a,
                 int lidx, int Ci, int Hi, int Wi, int Co, int Ho, int Wo) {
    const int NV = (STRIDE == 1) ? 6 : 9;  // input values needed per row for 4 outputs
    int WT = (Wo + 3) >> 2;
    int idx = blockIdx.x * blockDim.x + threadIdx.x;
    int total = B * Co * Ho * WT;
    if (idx >= total) return;
    int wt = idx % WT; int r = idx / WT;
    int ho = r % Ho;   r /= Ho;
    int co = r % Co;   int b = r / Co;
    int wo0 = wt << 2;
    int wbase = wo0 * STRIDE - 1;

    float acc[4] = {0.f, 0.f, 0.f, 0.f};
    const float* wco = wgt + (size_t)co * Ci * 9;

    for (int ci = 0; ci < Ci; ++ci) {
        const float* ip = in + (size_t)(b * Ci + ci) * Hi * Wi;
        const float* wk = wco + ci * 9;
#pragma unroll
        for (int kh = 0; kh < 3; ++kh) {
            int hi = ho * STRIDE + kh - 1;
            if ((unsigned)hi >= (unsigned)Hi) continue;
            const float* row = ip + hi * Wi;
            float v[9];
#pragma unroll
            for (int t = 0; t < NV; ++t) {
                int wi = wbase + t;
                v[t] = ((unsigned)wi < (unsigned)Wi) ? __ldg(row + wi) : 0.0f;
            }
            float w0 = __ldg(wk + kh * 3 + 0);
            float w1 = __ldg(wk + kh * 3 + 1);
            float w2 = __ldg(wk + kh * 3 + 2);
#pragma unroll
            for (int j = 0; j < 4; ++j) {
                acc[j] = fmaf(w0, v[j * STRIDE + 0], acc[j]);
                acc[j] = fmaf(w1, v[j * STRIDE + 1], acc[j]);
                acc[j] = fmaf(w2, v[j * STRIDE + 2], acc[j]);
            }
        }
    }

    float thr  = __ldg(thr_a + lidx);
    float leak = __ldg(leak_a + lidx);
    size_t ob = ((size_t)(b * Co + co) * Ho + ho) * Wo;
#pragma unroll
    for (int j = 0; j < 4; ++j) {
        int wo = wo0 + j;
        if (wo >= Wo) break;
        size_t oi = ob + wo;
        float d = acc[j];
        if (res) d += __ldg(res + oi);
        float m = fmaf(leak, mem[oi], d);
        float mth = m / thr - 1.0f;
        float s = (mth > 0.0f) ? 1.0f : 0.0f;
        mem[oi] = m - thr * s;
        out[oi] = mask ? s * __ldg(mask + oi) : s;
    }
}

// 1x1 conv, stride 2, pad 0 (residual shortcut, raw output - no LIF).
__global__ __launch_bounds__(256)
void conv1x1s2(const float* __restrict__ in, const float* __restrict__ wgt,
               float* __restrict__ out, int Ci, int Hi, int Wi,
               int Co, int Ho, int Wo) {
    int idx = blockIdx.x * blockDim.x + threadIdx.x;
    int total = B * Co * Ho * Wo;
    if (idx >= total) return;
    int wo = idx % Wo; int r = idx / Wo;
    int ho = r % Ho;   r /= Ho;
    int co = r % Co;   int b = r / Co;
    const float* wk = wgt + (size_t)co * Ci;
    float acc = 0.f;
    size_t ibase = (size_t)b * Ci * Hi * Wi + (size_t)(2 * ho) * Wi + 2 * wo;
    for (int ci = 0; ci < Ci; ++ci)
        acc = fmaf(__ldg(wk + ci), __ldg(in + ibase + (size_t)ci * Hi * Wi), acc);
    out[((size_t)(b * Co + co) * Ho + ho) * Wo + wo] = acc;
}

// 2x2 average pool
__global__ __launch_bounds__(256)
void avgpool2_kernel(const float* __restrict__ in, float* __restrict__ out,
                     int C, int Ho, int Wo) {
    int idx = blockIdx.x * blockDim.x + threadIdx.x;
    int total = B * C * Ho * Wo;
    if (idx >= total) return;
    int wo = idx % Wo; int r = idx / Wo;
    int ho = r % Ho;   r /= Ho;
    int c = r % C;     int b = r / C;
    int Wi = 2 * Wo;
    const float* p = in + ((size_t)(b * C + c) * 2 * Ho + 2 * ho) * Wi + 2 * wo;
    out[idx] = 0.25f * (p[0] + p[1] + p[Wi] + p[Wi + 1]);
}

// FC accumulate: out[b,j] += sum_k in[b,k] * wfc[j,k].  One warp per output.
__global__ __launch_bounds__(256)
void fc_acc(const float* __restrict__ in, const float* __restrict__ wfc,
            float* __restrict__ out) {
    int gw = (blockIdx.x * blockDim.x + threadIdx.x) >> 5;
    int lane = threadIdx.x & 31;
    if (gw >= B * 10) return;
    int b = gw / 10, j = gw % 10;
    const float* x = in + (size_t)b * 2048;
    const float* w = wfc + (size_t)j * 2048;
    float s = 0.f;
    for (int k = lane; k < 2048; k += 32) s = fmaf(x[k], w[k], s);
#pragma unroll
    for (int o = 16; o; o >>= 1) s += __shfl_down_sync(0xffffffffu, s, o);
    if (lane == 0) out[b * 10 + j] += s;
}

// -------------------------- host-side orchestration ------------------------

static void conv3(int stride, const float* in, const float* w, const float* res,
                  const float* mask, float* mem, float* out,
                  const float* thr, const float* leak, int lidx,
                  int Ci, int Hi, int Wi, int Co, int Ho, int Wo) {
    int total = B * Co * Ho * ((Wo + 3) / 4);
    int blocks = (total + 255) / 256;
    if (stride == 1)
        conv3x3_lif<1><<<blocks, 256>>>(in, w, res, mask, mem, out, thr, leak,
                                        lidx, Ci, Hi, Wi, Co, Ho, Wo);
    else
        conv3x3_lif<2><<<blocks, 256>>>(in, w, res, mask, mem, out, thr, leak,
                                        lidx, Ci, Hi, Wi, Co, Ho, Wo);
}

extern "C" void kernel_launch(void* const* d_in, const int* in_sizes, int n_in,
                              void* d_out, int out_size) {
    const float* x      = (const float*)d_in[0];
    const float* w_pre0 = (const float*)d_in[1];
    const float* w_pre1 = (const float*)d_in[2];
    const float* w_pre2 = (const float*)d_in[3];
    const float* w1a    = (const float*)d_in[4];
    const float* w1b    = (const float*)d_in[5];
    const float* w2a    = (const float*)d_in[6];
    const float* w2b    = (const float*)d_in[7];
    const float* w2i    = (const float*)d_in[8];
    const float* w3a    = (const float*)d_in[9];
    const float* w3b    = (const float*)d_in[10];
    const float* w3i    = (const float*)d_in[11];
    const float* w4a    = (const float*)d_in[12];
    const float* w4b    = (const float*)d_in[13];
    const float* w4i    = (const float*)d_in[14];
    const float* w_fc   = (const float*)d_in[15];
    const float* thr    = (const float*)d_in[16];
    const float* leak   = (const float*)d_in[17];
    const float* mask2  = (const float*)d_in[18];
    const float* mask5  = (const float*)d_in[19];
    const float* mask9  = (const float*)d_in[20];
    const float* mask11 = (const float*)d_in[21];
    const float* mask13 = (const float*)d_in[22];
    const float* mask15 = (const float*)d_in[23];

    float *pm, *pA, *pB, *pC;
    cudaGetSymbolAddress((void**)&pm, g_mem);
    cudaGetSymbolAddress((void**)&pA, g_A);
    cudaGetSymbolAddress((void**)&pB, g_B);
    cudaGetSymbolAddress((void**)&pC, g_C);

    float* m0  = pm + OFF_M0;
    float* m1  = pm + OFF_M1;
    float* m2  = pm + OFF_M2;
    float* m3  = pm + OFF_M3;
    float* m4  = pm + OFF_M4;
    float* m5  = pm + OFF_M5;
    float* m6  = pm + OFF_M6;
    float* m7  = pm + OFF_M7;
    float* m8  = pm + OFF_M8;
    float* m9  = pm + OFF_M9;
    float* m10 = pm + OFF_M10;

    // zero all membrane state + output accumulator
    zero_kernel<<<(MEM_TOTAL + 255) / 256, 256>>>(pm, (int)MEM_TOTAL);
    zero_kernel<<<2, 256>>>((float*)d_out, out_size);

    for (int t = 0; t < TSTEPS; ++t) {
        // pre-process
        conv3(1, x,  w_pre0, nullptr, mask2, m0, pA, thr, leak, 0, 3, 32, 32, 64, 32, 32);
        conv3(1, pA, w_pre1, nullptr, mask5, m1, pB, thr, leak, 1, 64, 32, 32, 64, 32, 32);
        conv3(1, pB, w_pre2, nullptr, nullptr, m2, pA, thr, leak, 2, 64, 32, 32, 64, 32, 32);
        {
            int total = B * 64 * 16 * 16;
            avgpool2_kernel<<<(total + 255) / 256, 256>>>(pA, pB, 64, 16, 16);
        }
        // layer1 (identity shortcut): inp = B
        conv3(1, pB, w1a, nullptr, mask9, m3, pA, thr, leak, 3, 64, 16, 16, 64, 16, 16);
        conv3(1, pA, w1b, pB, nullptr, m4, pC, thr, leak, 4, 64, 16, 16, 64, 16, 16);
        // layer2 (1x1 s2 shortcut): inp = C
        conv3(2, pC, w2a, nullptr, mask11, m5, pA, thr, leak, 5, 64, 16, 16, 128, 8, 8);
        {
            int total = B * 128 * 8 * 8;
            conv1x1s2<<<(total + 255) / 256, 256>>>(pC, w2i, pB, 64, 16, 16, 128, 8, 8);
        }
        conv3(1, pA, w2b, pB, nullptr, m6, pC, thr, leak, 6, 128, 8, 8, 128, 8, 8);
        // layer3: inp = C
        conv3(2, pC, w3a, nullptr, mask13, m7, pA, thr, leak, 7, 128, 8, 8, 256, 4, 4);
        {
            int total = B * 256 * 4 * 4;
            conv1x1s2<<<(total + 255) / 256, 256>>>(pC, w3i, pB, 128, 8, 8, 256, 4, 4);
        }
        conv3(1, pA, w3b, pB, nullptr, m8, pC, thr, leak, 8, 256, 4, 4, 256, 4, 4);
        // layer4: inp = C
        conv3(2, pC, w4a, nullptr, mask15, m9, pA, thr, leak, 9, 256, 4, 4, 512, 2, 2);
        {
            int total = B * 512 * 2 * 2;
            conv1x1s2<<<(total + 255) / 256, 256>>>(pC, w4i, pB, 256, 4, 4, 512, 2, 2);
        }
        conv3(1, pA, w4b, pB, nullptr, m10, pC, thr, leak, 10, 512, 2, 2, 512, 2, 2);
        // classifier accumulation
        fc_acc<<<40, 256>>>(pC, w_fc, (float*)d_out);
    }
}

// round 2
// speedup vs baseline: 1.4992x; 1.4992x over previous
#include <cuda_runtime.h>

// ---------------------------------------------------------------------------
// SNN ResNet forward, 8 timesteps, B=32. fp32 smem-tiled convolutions with
// fused LIF (leaky integrate-and-fire, soft reset), dropout masks, residuals.
// ---------------------------------------------------------------------------

#define B 32
#define TSTEPS 8

#define OFF_M0  0u
#define OFF_M1  2097152u
#define OFF_M2  4194304u
#define OFF_M3  6291456u
#define OFF_M4  6815744u
#define OFF_M5  7340032u
#define OFF_M6  7602176u
#define OFF_M7  7864320u
#define OFF_M8  7995392u
#define OFF_M9  8126464u
#define OFF_M10 8192000u
#define MEM_TOTAL 8257536u

__device__ float g_mem[MEM_TOTAL];
__device__ float g_A[2097152];
__device__ float g_B[2097152];
__device__ float g_C[2097152];

__global__ void zero_kernel(float* __restrict__ p, int n) {
    int i = blockIdx.x * blockDim.x + threadIdx.x;
    if (i < n) p[i] = 0.0f;
}

// ---------------------------------------------------------------------------
// Fused 3x3 conv (pad=1) + optional residual + LIF + optional dropout mask.
// Block covers: B_T batch images x CO_T output channels x whole spatial plane.
// Input chunk (CIC channels, with halo) and weight chunk staged in smem.
// Each thread owns a TH x TW output tile for one (b, co).
// ---------------------------------------------------------------------------
template<int H, int CI, int CO, int STRIDE, int CIC, int TH, int TW, int CO_T, int B_T>
__global__ __launch_bounds__(256)
void conv_fused(const float* __restrict__ in, const float* __restrict__ wgt,
                const float* __restrict__ res, const float* __restrict__ mask,
                float* __restrict__ mem, float* __restrict__ out,
                const float* __restrict__ thr_a, const float* __restrict__ leak_a,
                int lidx) {
    constexpr int HO = H / STRIDE;
    constexpr int WO = HO;
    constexpr int HI2 = H + 2;
    constexpr int WI2 = H + 2;
    constexpr int TILESW = WO / TW;
    constexpr int TILESH = HO / TH;
    constexpr int TILES = TILESH * TILESW;
    static_assert(TILES * CO_T * B_T == 256, "thread count must be 256");
    constexpr int IN_B = CIC * HI2 * WI2;       // floats per image chunk
    constexpr int IN_STRIDE = IN_B + 1;         // pad to break bank alignment
    constexpr int W_CO = CIC * 9;
    constexpr int W_STRIDE = W_CO + 1;
    constexpr int RH = (TH - 1) * STRIDE + 3;   // input rows touched per tile
    constexpr int RW = (TW - 1) * STRIDE + 3;   // input cols touched per tile

    __shared__ float s_in[B_T * IN_STRIDE];
    __shared__ float s_w[CO_T * W_STRIDE];

    const int tid = threadIdx.x;
    const int tile = tid % TILES;
    const int co_l = (tid / TILES) % CO_T;
    const int b_l  = tid / (TILES * CO_T);
    const int co_g = blockIdx.x % (CO / CO_T);
    const int b_g  = blockIdx.x / (CO / CO_T);
    const int b  = b_g * B_T + b_l;
    const int co = co_g * CO_T + co_l;
    const int oh0 = (tile / TILESW) * TH;
    const int ow0 = (tile % TILESW) * TW;

    float acc[TH * TW];
#pragma unroll
    for (int i = 0; i < TH * TW; ++i) acc[i] = 0.0f;

    const float* sin_b = s_in + b_l * IN_STRIDE;
    const float* sw_c  = s_w + co_l * W_STRIDE;

    for (int cc = 0; cc < CI / CIC; ++cc) {
        // --- cooperative stage: input chunk (with zero halo) ---
        for (int idx = tid; idx < B_T * IN_B; idx += 256) {
            int wi = idx % WI2; int r = idx / WI2;
            int hi = r % HI2;   r /= HI2;
            int ci = r % CIC;   int bl = r / CIC;
            int gh = hi - 1, gw = wi - 1;
            float v = 0.0f;
            if ((unsigned)gh < (unsigned)H && (unsigned)gw < (unsigned)H)
                v = in[(((size_t)(b_g * B_T + bl) * CI + cc * CIC + ci) * H + gh) * H + gw];
            s_in[bl * IN_STRIDE + ci * HI2 * WI2 + hi * WI2 + wi] = v;
        }
        // --- cooperative stage: weight chunk ---
        for (int idx = tid; idx < CO_T * W_CO; idx += 256) {
            int k = idx % 9; int r = idx / 9;
            int ci = r % CIC; int col = r / CIC;
            s_w[col * W_STRIDE + ci * 9 + k] =
                wgt[((size_t)(co_g * CO_T + col) * CI + cc * CIC + ci) * 9 + k];
        }
        __syncthreads();

        // --- compute: row-streamed register window ---
        for (int ci = 0; ci < CIC; ++ci) {
            const float* sp = sin_b + ci * HI2 * WI2 + (oh0 * STRIDE) * WI2 + ow0 * STRIDE;
            float w9[9];
#pragma unroll
            for (int k = 0; k < 9; ++k) w9[k] = sw_c[ci * 9 + k];
#pragma unroll
            for (int r = 0; r < RH; ++r) {
                float rowv[RW];
#pragma unroll
                for (int c = 0; c < RW; ++c) rowv[c] = sp[r * WI2 + c];
#pragma unroll
                for (int kh = 0; kh < 3; ++kh) {
                    if (r - kh >= 0 && (r - kh) % STRIDE == 0 && (r - kh) / STRIDE < TH) {
                        const int i = (r - kh) / STRIDE;
#pragma unroll
                        for (int kw = 0; kw < 3; ++kw)
#pragma unroll
                            for (int j = 0; j < TW; ++j)
                                acc[i * TW + j] = fmaf(w9[kh * 3 + kw],
                                                       rowv[j * STRIDE + kw],
                                                       acc[i * TW + j]);
                    }
                }
            }
        }
        __syncthreads();
    }

    // --- epilogue: residual + LIF + mask ---
    const float thr  = __ldg(thr_a + lidx);
    const float leak = __ldg(leak_a + lidx);
#pragma unroll
    for (int i = 0; i < TH; ++i) {
#pragma unroll
        for (int j = 0; j < TW; ++j) {
            size_t oi = (((size_t)b * CO + co) * HO + oh0 + i) * WO + ow0 + j;
            float d = acc[i * TW + j];
            if (res) d += __ldg(res + oi);
            float m = fmaf(leak, mem[oi], d);
            float mth = m / thr - 1.0f;
            float s = (mth > 0.0f) ? 1.0f : 0.0f;
            mem[oi] = m - thr * s;
            out[oi] = mask ? s * __ldg(mask + oi) : s;
        }
    }
}

// 1x1 conv, stride 2, pad 0 (residual shortcut, raw output - no LIF).
__global__ __launch_bounds__(256)
void conv1x1s2(const float* __restrict__ in, const float* __restrict__ wgt,
               float* __restrict__ out, int Ci, int Hi, int Wi,
               int Co, int Ho, int Wo) {
    int idx = blockIdx.x * blockDim.x + threadIdx.x;
    int total = B * Co * Ho * Wo;
    if (idx >= total) return;
    int wo = idx % Wo; int r = idx / Wo;
    int ho = r % Ho;   r /= Ho;
    int co = r % Co;   int b = r / Co;
    const float* wk = wgt + (size_t)co * Ci;
    float acc = 0.f;
    size_t ibase = (size_t)b * Ci * Hi * Wi + (size_t)(2 * ho) * Wi + 2 * wo;
    for (int ci = 0; ci < Ci; ++ci)
        acc = fmaf(__ldg(wk + ci), __ldg(in + ibase + (size_t)ci * Hi * Wi), acc);
    out[((size_t)(b * Co + co) * Ho + ho) * Wo + wo] = acc;
}

// 2x2 average pool
__global__ __launch_bounds__(256)
void avgpool2_kernel(const float* __restrict__ in, float* __restrict__ out,
                     int C, int Ho, int Wo) {
    int idx = blockIdx.x * blockDim.x + threadIdx.x;
    int total = B * C * Ho * Wo;
    if (idx >= total) return;
    int wo = idx % Wo; int r = idx / Wo;
    int ho = r % Ho;   r /= Ho;
    int c = r % C;     int b = r / C;
    int Wi = 2 * Wo;
    const float* p = in + ((size_t)(b * C + c) * 2 * Ho + 2 * ho) * Wi + 2 * wo;
    out[idx] = 0.25f * (p[0] + p[1] + p[Wi] + p[Wi + 1]);
}

// FC accumulate: out[b,j] += sum_k in[b,k] * wfc[j,k].  One warp per output.
__global__ __launch_bounds__(256)
void fc_acc(const float* __restrict__ in, const float* __restrict__ wfc,
            float* __restrict__ out) {
    int gw = (blockIdx.x * blockDim.x + threadIdx.x) >> 5;
    int lane = threadIdx.x & 31;
    if (gw >= B * 10) return;
    int b = gw / 10, j = gw % 10;
    const float* x = in + (size_t)b * 2048;
    const float* w = wfc + (size_t)j * 2048;
    float s = 0.f;
    for (int k = lane; k < 2048; k += 32) s = fmaf(x[k], w[k], s);
#pragma unroll
    for (int o = 16; o; o >>= 1) s += __shfl_down_sync(0xffffffffu, s, o);
    if (lane == 0) out[b * 10 + j] += s;
}

// -------------------------- host-side orchestration ------------------------

extern "C" void kernel_launch(void* const* d_in, const int* in_sizes, int n_in,
                              void* d_out, int out_size) {
    const float* x      = (const float*)d_in[0];
    const float* w_pre0 = (const float*)d_in[1];
    const float* w_pre1 = (const float*)d_in[2];
    const float* w_pre2 = (const float*)d_in[3];
    const float* w1a    = (const float*)d_in[4];
    const float* w1b    = (const float*)d_in[5];
    const float* w2a    = (const float*)d_in[6];
    const float* w2b    = (const float*)d_in[7];
    const float* w2i    = (const float*)d_in[8];
    const float* w3a    = (const float*)d_in[9];
    const float* w3b    = (const float*)d_in[10];
    const float* w3i    = (const float*)d_in[11];
    const float* w4a    = (const float*)d_in[12];
    const float* w4b    = (const float*)d_in[13];
    const float* w4i    = (const float*)d_in[14];
    const float* w_fc   = (const float*)d_in[15];
    const float* thr    = (const float*)d_in[16];
    const float* leak   = (const float*)d_in[17];
    const float* mask2  = (const float*)d_in[18];
    const float* mask5  = (const float*)d_in[19];
    const float* mask9  = (const float*)d_in[20];
    const float* mask11 = (const float*)d_in[21];
    const float* mask13 = (const float*)d_in[22];
    const float* mask15 = (const float*)d_in[23];

    float *pm, *pA, *pB, *pC;
    cudaGetSymbolAddress((void**)&pm, g_mem);
    cudaGetSymbolAddress((void**)&pA, g_A);
    cudaGetSymbolAddress((void**)&pB, g_B);
    cudaGetSymbolAddress((void**)&pC, g_C);

    float* m0  = pm + OFF_M0;
    float* m1  = pm + OFF_M1;
    float* m2  = pm + OFF_M2;
    float* m3  = pm + OFF_M3;
    float* m4  = pm + OFF_M4;
    float* m5  = pm + OFF_M5;
    float* m6  = pm + OFF_M6;
    float* m7  = pm + OFF_M7;
    float* m8  = pm + OFF_M8;
    float* m9  = pm + OFF_M9;
    float* m10 = pm + OFF_M10;

    zero_kernel<<<(MEM_TOTAL + 255) / 256, 256>>>(pm, (int)MEM_TOTAL);
    zero_kernel<<<2, 256>>>((float*)d_out, out_size);

    for (int t = 0; t < TSTEPS; ++t) {
        // pre-process (32x32, 64ch)
        conv_fused<32, 3, 64, 1, 3, 4, 4, 4, 1><<<512, 256>>>(
            x, w_pre0, nullptr, mask2, m0, pA, thr, leak, 0);
        conv_fused<32, 64, 64, 1, 8, 4, 4, 4, 1><<<512, 256>>>(
            pA, w_pre1, nullptr, mask5, m1, pB, thr, leak, 1);
        conv_fused<32, 64, 64, 1, 8, 4, 4, 4, 1><<<512, 256>>>(
            pB, w_pre2, nullptr, nullptr, m2, pA, thr, leak, 2);
        avgpool2_kernel<<<(B * 64 * 16 * 16 + 255) / 256, 256>>>(pA, pB, 64, 16, 16);

        // layer1 (identity shortcut): inp = pB
        conv_fused<16, 64, 64, 1, 16, 4, 4, 16, 1><<<128, 256>>>(
            pB, w1a, nullptr, mask9, m3, pA, thr, leak, 3);
        conv_fused<16, 64, 64, 1, 16, 4, 4, 16, 1><<<128, 256>>>(
            pA, w1b, pB, nullptr, m4, pC, thr, leak, 4);

        // layer2 (1x1 s2 shortcut): inp = pC
        conv_fused<16, 64, 128, 2, 8, 2, 4, 32, 1><<<128, 256>>>(
            pC, w2a, nullptr, mask11, m5, pA, thr, leak, 5);
        conv1x1s2<<<(B * 128 * 8 * 8 + 255) / 256, 256>>>(pC, w2i, pB, 64, 16, 16, 128, 8, 8);
        conv_fused<8, 128, 128, 1, 16, 4, 4, 32, 2><<<64, 256>>>(
            pA, w2b, pB, nullptr, m6, pC, thr, leak, 6);

        // layer3: inp = pC
        conv_fused<8, 128, 256, 2, 8, 2, 4, 32, 4><<<64, 256>>>(
            pC, w3a, nullptr, mask13, m7, pA, thr, leak, 7);
        conv1x1s2<<<(B * 256 * 4 * 4 + 255) / 256, 256>>>(pC, w3i, pB, 128, 8, 8, 256, 4, 4);
        conv_fused<4, 256, 256, 1, 16, 4, 4, 32, 8><<<32, 256>>>(
            pA, w3b, pB, nullptr, m8, pC, thr, leak, 8);

        // layer4: inp = pC
        conv_fused<4, 256, 512, 2, 16, 2, 2, 32, 8><<<64, 256>>>(
            pC, w4a, nullptr, mask15, m9, pA, thr, leak, 9);
        conv1x1s2<<<(B * 512 * 2 * 2 + 255) / 256, 256>>>(pC, w4i, pB, 256, 4, 4, 512, 2, 2);
        conv_fused<2, 512, 512, 1, 16, 2, 2, 32, 8><<<64, 256>>>(
            pA, w4b, pB, nullptr, m10, pC, thr, leak, 10);

        // classifier accumulation
        fc_acc<<<40, 256>>>(pC, w_fc, (float*)d_out);
    }
}

// round 3
// speedup vs baseline: 1.6789x; 1.1199x over previous
#include <cuda_runtime.h>

// ---------------------------------------------------------------------------
// SNN ResNet forward, 8 timesteps, B=32. fp32 smem-tiled convolutions with
// fused LIF, dropout masks, residuals, and fused 1x1-s2 shortcut convs.
// ---------------------------------------------------------------------------

#define B 32
#define TSTEPS 8

#define OFF_M0  0u
#define OFF_M1  2097152u
#define OFF_M2  4194304u
#define OFF_M3  6291456u
#define OFF_M4  6815744u
#define OFF_M5  7340032u
#define OFF_M6  7602176u
#define OFF_M7  7864320u
#define OFF_M8  7995392u
#define OFF_M9  8126464u
#define OFF_M10 8192000u
#define MEM_TOTAL 8257536u

__device__ float g_mem[MEM_TOTAL];
__device__ float g_A[2097152];
__device__ float g_B[2097152];
__device__ float g_C[2097152];

__global__ void zero_kernel(float* __restrict__ p, int n) {
    int i = blockIdx.x * blockDim.x + threadIdx.x;
    if (i < n) p[i] = 0.0f;
}

// ---------------------------------------------------------------------------
// Fused 3x3 conv (pad=1) + optional (residual | fused 1x1-s2 shortcut conv)
// + LIF + optional dropout mask.
// Block covers B_T images x CO_T output channels x the full spatial plane.
// SC_CI > 0: residual computed inline as 1x1 stride-2 conv over sc_in.
// ---------------------------------------------------------------------------
template<int H, int CI, int CO, int STRIDE, int CIC, int TH, int TW,
         int CO_T, int B_T, int NT, int SC_CI>
__global__ __launch_bounds__(NT)
void conv_fused(const float* __restrict__ in, const float* __restrict__ wgt,
                const float* __restrict__ res, const float* __restrict__ mask,
                const float* __restrict__ sc_in, const float* __restrict__ sc_w,
                float* __restrict__ mem, float* __restrict__ out,
                const float* __restrict__ thr_a, const float* __restrict__ leak_a,
                int lidx) {
    constexpr int HO = H / STRIDE;
    constexpr int WO = HO;
    constexpr int TILESH = HO / TH;
    constexpr int TILESW = WO / TW;
    constexpr int TILES = TILESH * TILESW;
    static_assert(TILES * CO_T * B_T == NT, "thread count mismatch");
    static_assert((TW * STRIDE) % 4 == 0 || TILESW == 1, "LDS.128 alignment");
    constexpr int SW = ((H + 2 + 3) / 4) * 4;   // smem row stride (interior at col 1)
    constexpr int HI2 = H + 2;
    constexpr int IN_CH = HI2 * SW;
    constexpr int IN_IMG = CIC * IN_CH;
    constexpr int IN_TOT = B_T * IN_IMG;
    constexpr int RH = (TH - 1) * STRIDE + 3;
    constexpr int RW = (TW - 1) * STRIDE + 3;
    constexpr int NV4 = (RW + 3) / 4;
    constexpr int CHUNKS = CI / CIC;

    __shared__ alignas(16) float s_in[IN_TOT];
    __shared__ alignas(16) float s_w[CO_T * CIC * 9];

    const int tid = threadIdx.x;
    const int tile = tid % TILES;
    const int co_l = (tid / TILES) % CO_T;
    const int b_l  = tid / (TILES * CO_T);
    const int co_g = blockIdx.x % (CO / CO_T);
    const int b_g  = blockIdx.x / (CO / CO_T);
    const int b  = b_g * B_T + b_l;
    const int co = co_g * CO_T + co_l;
    const int oh0 = (tile / TILESW) * TH;
    const int ow0 = (tile % TILESW) * TW;

    // zero whole input smem once: halo ring stays zero across all chunks
    {
        const float4 z4 = make_float4(0.f, 0.f, 0.f, 0.f);
        for (int i = tid * 4; i < IN_TOT; i += NT * 4)
            *reinterpret_cast<float4*>(s_in + i) = z4;
    }
    __syncthreads();

    float acc[TH * TW];
#pragma unroll
    for (int i = 0; i < TH * TW; ++i) acc[i] = 0.0f;

    const float* sw_c = s_w + co_l * CIC * 9;

    for (int cc = 0; cc < CHUNKS; ++cc) {
        // --- stage input rows (float4 GMEM loads, pow2 index math) ---
        constexpr int ROWS = B_T * CIC * H;
        for (int r = tid; r < ROWS; r += NT) {
            int bl, rr;
            if (B_T == 1) { bl = 0; rr = r; }
            else { bl = r / (CIC * H); rr = r - bl * (CIC * H); }
            const int ci = rr / H;
            const int h  = rr % H;
            const float* src = in + (((size_t)(b_g * B_T + bl) * CI + cc * CIC + ci) * H + h) * H;
            float* dst = s_in + bl * IN_IMG + ci * IN_CH + (h + 1) * SW + 1;
            if (H >= 4) {
#pragma unroll
                for (int q = 0; q < H / 4; ++q) {
                    float4 v = __ldg(reinterpret_cast<const float4*>(src) + q);
                    dst[4 * q + 0] = v.x; dst[4 * q + 1] = v.y;
                    dst[4 * q + 2] = v.z; dst[4 * q + 3] = v.w;
                }
            } else {
#pragma unroll
                for (int q = 0; q < H; ++q) dst[q] = __ldg(src + q);
            }
        }
        // --- stage weights ---
        for (int i = tid; i < CO_T * CIC * 9; i += NT) {
            int k = i % 9; int rest = i / 9;
            int ci = rest % CIC; int col = rest / CIC;
            s_w[(col * CIC + ci) * 9 + k] =
                __ldg(wgt + ((size_t)(co_g * CO_T + col) * CI + cc * CIC + ci) * 9 + k);
        }
        __syncthreads();

        // --- compute ---
        const float* sin_b = s_in + b_l * IN_IMG + (oh0 * STRIDE) * SW + ow0 * STRIDE;
        for (int ci = 0; ci < CIC; ++ci) {
            float w9[9];
#pragma unroll
            for (int k = 0; k < 9; ++k) w9[k] = sw_c[ci * 9 + k];
            const float* sp = sin_b + ci * IN_CH;
#pragma unroll
            for (int r = 0; r < RH; ++r) {
                float v[NV4 * 4];
#pragma unroll
                for (int q = 0; q < NV4; ++q)
                    *reinterpret_cast<float4*>(v + 4 * q) =
                        *reinterpret_cast<const float4*>(sp + r * SW + 4 * q);
#pragma unroll
                for (int kh = 0; kh < 3; ++kh) {
                    if (r - kh >= 0 && (r - kh) % STRIDE == 0 && (r - kh) / STRIDE < TH) {
                        const int i = (r - kh) / STRIDE;
#pragma unroll
                        for (int kw = 0; kw < 3; ++kw)
#pragma unroll
                            for (int j = 0; j < TW; ++j)
                                acc[i * TW + j] = fmaf(w9[kh * 3 + kw],
                                                       v[j * STRIDE + kw],
                                                       acc[i * TW + j]);
                    }
                }
            }
        }
        __syncthreads();
    }

    // --- epilogue: shortcut/residual + LIF + mask ---
    const float thr  = __ldg(thr_a + lidx);
    const float leak = __ldg(leak_a + lidx);

    float rsum[TH * TW];
    if (SC_CI > 0) {
#pragma unroll
        for (int i = 0; i < TH * TW; ++i) rsum[i] = 0.0f;
        const float* wp = sc_w + (size_t)co * SC_CI;
        for (int ci = 0; ci < SC_CI; ++ci) {
            float wv = __ldg(wp + ci);
            const float* ip = sc_in + ((size_t)b * SC_CI + ci) * (4 * HO * WO);
#pragma unroll
            for (int i = 0; i < TH; ++i)
#pragma unroll
                for (int j = 0; j < TW; ++j)
                    rsum[i * TW + j] = fmaf(wv,
                        __ldg(ip + (2 * (oh0 + i)) * (2 * WO) + 2 * (ow0 + j)),
                        rsum[i * TW + j]);
        }
    }

#pragma unroll
    for (int i = 0; i < TH; ++i) {
#pragma unroll
        for (int j = 0; j < TW; ++j) {
            size_t oi = (((size_t)b * CO + co) * HO + oh0 + i) * WO + ow0 + j;
            float d = acc[i * TW + j];
            if (SC_CI > 0) d += rsum[i * TW + j];
            else if (res) d += __ldg(res + oi);
            float m = fmaf(leak, mem[oi], d);
            float mth = m / thr - 1.0f;
            float s = (mth > 0.0f) ? 1.0f : 0.0f;
            mem[oi] = m - thr * s;
            out[oi] = mask ? s * __ldg(mask + oi) : s;
        }
    }
}

// 2x2 average pool
__global__ __launch_bounds__(256)
void avgpool2_kernel(const float* __restrict__ in, float* __restrict__ out,
                     int C, int Ho, int Wo) {
    int idx = blockIdx.x * blockDim.x + threadIdx.x;
    int total = B * C * Ho * Wo;
    if (idx >= total) return;
    int wo = idx % Wo; int r = idx / Wo;
    int ho = r % Ho;   r /= Ho;
    int c = r % C;     int b = r / C;
    int Wi = 2 * Wo;
    const float* p = in + ((size_t)(b * C + c) * 2 * Ho + 2 * ho) * Wi + 2 * wo;
    out[idx] = 0.25f * (p[0] + p[1] + p[Wi] + p[Wi + 1]);
}

// FC accumulate: out[b,j] += sum_k in[b,k] * wfc[j,k].  One warp per output.
__global__ __launch_bounds__(256)
void fc_acc(const float* __restrict__ in, const float* __restrict__ wfc,
            float* __restrict__ out) {
    int gw = (blockIdx.x * blockDim.x + threadIdx.x) >> 5;
    int lane = threadIdx.x & 31;
    if (gw >= B * 10) return;
    int b = gw / 10, j = gw % 10;
    const float* x = in + (size_t)b * 2048;
    const float* w = wfc + (size_t)j * 2048;
    float s = 0.f;
    for (int k = lane; k < 2048; k += 32) s = fmaf(x[k], w[k], s);
#pragma unroll
    for (int o = 16; o; o >>= 1) s += __shfl_down_sync(0xffffffffu, s, o);
    if (lane == 0) out[b * 10 + j] += s;
}

// -------------------------- host-side orchestration ------------------------

extern "C" void kernel_launch(void* const* d_in, const int* in_sizes, int n_in,
                              void* d_out, int out_size) {
    const float* x      = (const float*)d_in[0];
    const float* w_pre0 = (const float*)d_in[1];
    const float* w_pre1 = (const float*)d_in[2];
    const float* w_pre2 = (const float*)d_in[3];
    const float* w1a    = (const float*)d_in[4];
    const float* w1b    = (const float*)d_in[5];
    const float* w2a    = (const float*)d_in[6];
    const float* w2b    = (const float*)d_in[7];
    const float* w2i    = (const float*)d_in[8];
    const float* w3a    = (const float*)d_in[9];
    const float* w3b    = (const float*)d_in[10];
    const float* w3i    = (const float*)d_in[11];
    const float* w4a    = (const float*)d_in[12];
    const float* w4b    = (const float*)d_in[13];
    const float* w4i    = (const float*)d_in[14];
    const float* w_fc   = (const float*)d_in[15];
    const float* thr    = (const float*)d_in[16];
    const float* leak   = (const float*)d_in[17];
    const float* mask2  = (const float*)d_in[18];
    const float* mask5  = (const float*)d_in[19];
    const float* mask9  = (const float*)d_in[20];
    const float* mask11 = (const float*)d_in[21];
    const float* mask13 = (const float*)d_in[22];
    const float* mask15 = (const float*)d_in[23];

    float *pm, *pA, *pB, *pC;
    cudaGetSymbolAddress((void**)&pm, g_mem);
    cudaGetSymbolAddress((void**)&pA, g_A);
    cudaGetSymbolAddress((void**)&pB, g_B);
    cudaGetSymbolAddress((void**)&pC, g_C);

    float* m0  = pm + OFF_M0;
    float* m1  = pm + OFF_M1;
    float* m2  = pm + OFF_M2;
    float* m3  = pm + OFF_M3;
    float* m4  = pm + OFF_M4;
    float* m5  = pm + OFF_M5;
    float* m6  = pm + OFF_M6;
    float* m7  = pm + OFF_M7;
    float* m8  = pm + OFF_M8;
    float* m9  = pm + OFF_M9;
    float* m10 = pm + OFF_M10;

    zero_kernel<<<(MEM_TOTAL + 255) / 256, 256>>>(pm, (int)MEM_TOTAL);
    zero_kernel<<<2, 256>>>((float*)d_out, out_size);

    for (int t = 0; t < TSTEPS; ++t) {
        // pre-process (32x32, 64ch)
        conv_fused<32, 3, 64, 1, 3, 4, 4, 4, 1, 256, 0><<<512, 256>>>(
            x, w_pre0, nullptr, mask2, nullptr, nullptr, m0, pA, thr, leak, 0);
        conv_fused<32, 64, 64, 1, 8, 4, 4, 4, 1, 256, 0><<<512, 256>>>(
            pA, w_pre1, nullptr, mask5, nullptr, nullptr, m1, pB, thr, leak, 1);
        conv_fused<32, 64, 64, 1, 8, 4, 4, 4, 1, 256, 0><<<512, 256>>>(
            pB, w_pre2, nullptr, nullptr, nullptr, nullptr, m2, pA, thr, leak, 2);
        avgpool2_kernel<<<(B * 64 * 16 * 16 + 255) / 256, 256>>>(pA, pB, 64, 16, 16);

        // layer1 (identity shortcut)
        conv_fused<16, 64, 64, 1, 16, 4, 4, 16, 1, 256, 0><<<128, 256>>>(
            pB, w1a, nullptr, mask9, nullptr, nullptr, m3, pC, thr, leak, 3);
        conv_fused<16, 64, 64, 1, 16, 4, 4, 16, 1, 256, 0><<<128, 256>>>(
            pC, w1b, pB, nullptr, nullptr, nullptr, m4, pA, thr, leak, 4);

        // layer2 (fused 1x1-s2 shortcut in conv-b)
        conv_fused<16, 64, 128, 2, 8, 2, 4, 16, 2, 256, 0><<<128, 256>>>(
            pA, w2a, nullptr, mask11, nullptr, nullptr, m5, pB, thr, leak, 5);
        conv_fused<8, 128, 128, 1, 16, 4, 4, 16, 2, 128, 64><<<128, 128>>>(
            pB, w2b, nullptr, nullptr, pA, w2i, m6, pC, thr, leak, 6);

        // layer3
        conv_fused<8, 128, 256, 2, 16, 2, 2, 16, 2, 128, 0><<<256, 128>>>(
            pC, w3a, nullptr, mask13, nullptr, nullptr, m7, pA, thr, leak, 7);
        conv_fused<4, 256, 256, 1, 16, 2, 4, 32, 2, 128, 128><<<128, 128>>>(
            pA, w3b, nullptr, nullptr, pC, w3i, m8, pB, thr, leak, 8);

        // layer4
        conv_fused<4, 256, 512, 2, 16, 2, 2, 32, 4, 128, 0><<<128, 128>>>(
            pB, w4a, nullptr, mask15, nullptr, nullptr, m9, pC, thr, leak, 9);
        conv_fused<2, 512, 512, 1, 32, 1, 2, 32, 2, 128, 256><<<256, 128>>>(
            pC, w4b, nullptr, nullptr, pB, w4i, m10, pA, thr, leak, 10);

        // classifier accumulation
        fc_acc<<<40, 256>>>(pA, w_fc, (float*)d_out);
    }
}

// round 4
// speedup vs baseline: 3.1762x; 1.8918x over previous
#include <cuda_runtime.h>
#include <cuda_pipeline.h>

// ---------------------------------------------------------------------------
// SNN ResNet forward, 8 timesteps, B=32. fp32 smem-tiled convs with
// cp.async double-buffered staging, fused LIF, masks, residuals,
// and fused 1x1-s2 shortcut convolutions.
// ---------------------------------------------------------------------------

#define B 32
#define TSTEPS 8

#define OFF_M0  0u
#define OFF_M1  2097152u
#define OFF_M2  4194304u
#define OFF_M3  6291456u
#define OFF_M4  6815744u
#define OFF_M5  7340032u
#define OFF_M6  7602176u
#define OFF_M7  7864320u
#define OFF_M8  7995392u
#define OFF_M9  8126464u
#define OFF_M10 8192000u
#define MEM_TOTAL 8257536u

__device__ float g_mem[MEM_TOTAL];
__device__ float g_A[2097152];
__device__ float g_B[2097152];
__device__ float g_C[2097152];

__global__ void zero_kernel(float* __restrict__ p, int n) {
    int i = blockIdx.x * blockDim.x + threadIdx.x;
    if (i < n) p[i] = 0.0f;
}

// ---------------------------------------------------------------------------
// Fused 3x3 conv (pad=1) + (residual | fused 1x1-s2 shortcut) + LIF + mask.
// Double-buffered cp.async staging of input chunks and weight chunks.
// ---------------------------------------------------------------------------
template<int H, int CI, int CO, int STRIDE, int CIC, int TH, int TW,
         int CO_T, int B_T, int NT, int SC_CI>
__global__ __launch_bounds__(NT)
void conv_fused(const float* __restrict__ in, const float* __restrict__ wgt,
                const float* __restrict__ res, const float* __restrict__ mask,
                const float* __restrict__ sc_in, const float* __restrict__ sc_w,
                float* __restrict__ mem, float* __restrict__ out,
                const float* __restrict__ thr_a, const float* __restrict__ leak_a,
                int lidx) {
    constexpr int HO = H / STRIDE;
    constexpr int WO = HO;
    constexpr int TILESH = HO / TH;
    constexpr int TILESW = WO / TW;
    constexpr int TILES = TILESH * TILESW;
    static_assert(TILES * CO_T * B_T == NT, "thread count mismatch");
    static_assert((TW * STRIDE) % 4 == 0 || TILESW == 1, "LDS.128 alignment");
    constexpr int RH = (TH - 1) * STRIDE + 3;
    constexpr int RW = (TW - 1) * STRIDE + 3;
    constexpr int NV4 = (RW + 3) / 4;
    constexpr int SWMIN = (H + 2 > NV4 * 4) ? (H + 2) : (NV4 * 4);
    constexpr int SW = ((SWMIN + 3) / 4) * 4;   // smem row stride (interior col 1)
    constexpr int HI2 = H + 2;
    constexpr int IN_CH = HI2 * SW;
    constexpr int IN_IMG = CIC * IN_CH;
    constexpr int IN_TOT = B_T * IN_IMG;
    constexpr int W_TOT = CO_T * CIC * 9;
    constexpr int CHUNKS = CI / CIC;

    __shared__ alignas(16) float s_in[2][IN_TOT];
    __shared__ alignas(16) float s_w[2][W_TOT];

    const int tid = threadIdx.x;
    const int tile = tid % TILES;
    const int co_l = (tid / TILES) % CO_T;
    const int b_l  = tid / (TILES * CO_T);
    const int co_g = blockIdx.x % (CO / CO_T);
    const int b_g  = blockIdx.x / (CO / CO_T);
    const int b  = b_g * B_T + b_l;
    const int co = co_g * CO_T + co_l;
    const int oh0 = (tile / TILESW) * TH;
    const int ow0 = (tile % TILESW) * TW;

    // zero both input buffers once: halo / padding stays zero for all chunks
    {
        const float4 z4 = make_float4(0.f, 0.f, 0.f, 0.f);
        for (int i = tid * 4; i < IN_TOT; i += NT * 4) {
            *reinterpret_cast<float4*>(&s_in[0][i]) = z4;
            *reinterpret_cast<float4*>(&s_in[1][i]) = z4;
        }
    }
    __syncthreads();

    // stage chunk cc into buffer buf (interior elements + weights), async
    auto stage = [&](int buf, int cc) {
        constexpr int NE = B_T * CIC * H * H;
        for (int e = tid; e < NE; e += NT) {
            const int wq = e % H;
            int r = e / H;
            const int h = r % H; r /= H;
            const int ci = r % CIC;
            const int bl = r / CIC;
            const float* src = in + (((size_t)(b_g * B_T + bl) * CI + cc * CIC + ci) * H + h) * H + wq;
            float* dst = &s_in[buf][bl * IN_IMG + ci * IN_CH + (h + 1) * SW + 1 + wq];
            __pipeline_memcpy_async(dst, src, 4);
        }
        for (int e = tid; e < W_TOT; e += NT) {
            const int rem = e % (CIC * 9);
            const int col = e / (CIC * 9);
            const float* src = wgt + ((size_t)(co_g * CO_T + col) * CI + cc * CIC) * 9 + rem;
            __pipeline_memcpy_async(&s_w[buf][col * CIC * 9 + rem], src, 4);
        }
    };

    float acc[TH * TW];
#pragma unroll
    for (int i = 0; i < TH * TW; ++i) acc[i] = 0.0f;

    stage(0, 0);
    __pipeline_commit();

    for (int cc = 0; cc < CHUNKS; ++cc) {
        const int cur = cc & 1;
        if (cc + 1 < CHUNKS) {
            stage(cur ^ 1, cc + 1);
            __pipeline_commit();
            __pipeline_wait_prior(1);
        } else {
            __pipeline_wait_prior(0);
        }
        __syncthreads();

        const float* sin_b = &s_in[cur][b_l * IN_IMG + (oh0 * STRIDE) * SW + ow0 * STRIDE];
        const float* sw_c  = &s_w[cur][co_l * CIC * 9];
        for (int ci = 0; ci < CIC; ++ci) {
            float w9[9];
#pragma unroll
            for (int k = 0; k < 9; ++k) w9[k] = sw_c[ci * 9 + k];
            const float* sp = sin_b + ci * IN_CH;
#pragma unroll
            for (int r = 0; r < RH; ++r) {
                float v[NV4 * 4];
#pragma unroll
                for (int q = 0; q < NV4; ++q)
                    *reinterpret_cast<float4*>(v + 4 * q) =
                        *reinterpret_cast<const float4*>(sp + r * SW + 4 * q);
#pragma unroll
                for (int kh = 0; kh < 3; ++kh) {
                    if (r - kh >= 0 && (r - kh) % STRIDE == 0 && (r - kh) / STRIDE < TH) {
                        const int i = (r - kh) / STRIDE;
#pragma unroll
                        for (int kw = 0; kw < 3; ++kw)
#pragma unroll
                            for (int j = 0; j < TW; ++j)
                                acc[i * TW + j] = fmaf(w9[kh * 3 + kw],
                                                       v[j * STRIDE + kw],
                                                       acc[i * TW + j]);
                    }
                }
            }
        }
        __syncthreads();
    }

    // --- epilogue: shortcut/residual + LIF + mask ---
    const float thr  = __ldg(thr_a + lidx);
    const float leak = __ldg(leak_a + lidx);

    float rsum[TH * TW];
    if (SC_CI > 0) {
#pragma unroll
        for (int i = 0; i < TH * TW; ++i) rsum[i] = 0.0f;
        const float* wp = sc_w + (size_t)co * SC_CI;
        for (int ci = 0; ci < SC_CI; ++ci) {
            float wv = __ldg(wp + ci);
            const float* ip = sc_in + ((size_t)b * SC_CI + ci) * (4 * HO * WO);
#pragma unroll
            for (int i = 0; i < TH; ++i)
#pragma unroll
                for (int j = 0; j < TW; ++j)
                    rsum[i * TW + j] = fmaf(wv,
                        __ldg(ip + (2 * (oh0 + i)) * (2 * WO) + 2 * (ow0 + j)),
                        rsum[i * TW + j]);
        }
    }

#pragma unroll
    for (int i = 0; i < TH; ++i) {
#pragma unroll
        for (int j = 0; j < TW; ++j) {
            size_t oi = (((size_t)b * CO + co) * HO + oh0 + i) * WO + ow0 + j;
            float d = acc[i * TW + j];
            if (SC_CI > 0) d += rsum[i * TW + j];
            else if (res) d += __ldg(res + oi);
            float m = fmaf(leak, mem[oi], d);
            float mth = m / thr - 1.0f;
            float s = (mth > 0.0f) ? 1.0f : 0.0f;
            mem[oi] = m - thr * s;
            out[oi] = mask ? s * __ldg(mask + oi) : s;
        }
    }
}

// 2x2 average pool
__global__ __launch_bounds__(256)
void avgpool2_kernel(const float* __restrict__ in, float* __restrict__ out,
                     int C, int Ho, int Wo) {
    int idx = blockIdx.x * blockDim.x + threadIdx.x;
    int total = B * C * Ho * Wo;
    if (idx >= total) return;
    int wo = idx % Wo; int r = idx / Wo;
    int ho = r % Ho;   r /= Ho;
    int c = r % C;     int b = r / C;
    int Wi = 2 * Wo;
    const float* p = in + ((size_t)(b * C + c) * 2 * Ho + 2 * ho) * Wi + 2 * wo;
    out[idx] = 0.25f * (p[0] + p[1] + p[Wi] + p[Wi + 1]);
}

// FC accumulate: out[b,j] += sum_k in[b,k] * wfc[j,k].  One warp per output.
__global__ __launch_bounds__(256)
void fc_acc(const float* __restrict__ in, const float* __restrict__ wfc,
            float* __restrict__ out) {
    int gw = (blockIdx.x * blockDim.x + threadIdx.x) >> 5;
    int lane = threadIdx.x & 31;
    if (gw >= B * 10) return;
    int b = gw / 10, j = gw % 10;
    const float* x = in + (size_t)b * 2048;
    const float* w = wfc + (size_t)j * 2048;
    float s = 0.f;
    for (int k = lane; k < 2048; k += 32) s = fmaf(x[k], w[k], s);
#pragma unroll
    for (int o = 16; o; o >>= 1) s += __shfl_down_sync(0xffffffffu, s, o);
    if (lane == 0) out[b * 10 + j] += s;
}

// -------------------------- host-side orchestration ------------------------

extern "C" void kernel_launch(void* const* d_in, const int* in_sizes, int n_in,
                              void* d_out, int out_size) {
    const float* x      = (const float*)d_in[0];
    const float* w_pre0 = (const float*)d_in[1];
    const float* w_pre1 = (const float*)d_in[2];
    const float* w_pre2 = (const float*)d_in[3];
    const float* w1a    = (const float*)d_in[4];
    const float* w1b    = (const float*)d_in[5];
    const float* w2a    = (const float*)d_in[6];
    const float* w2b    = (const float*)d_in[7];
    const float* w2i    = (const float*)d_in[8];
    const float* w3a    = (const float*)d_in[9];
    const float* w3b    = (const float*)d_in[10];
    const float* w3i    = (const float*)d_in[11];
    const float* w4a    = (const float*)d_in[12];
    const float* w4b    = (const float*)d_in[13];
    const float* w4i    = (const float*)d_in[14];
    const float* w_fc   = (const float*)d_in[15];
    const float* thr    = (const float*)d_in[16];
    const float* leak   = (const float*)d_in[17];
    const float* mask2  = (const float*)d_in[18];
    const float* mask5  = (const float*)d_in[19];
    const float* mask9  = (const float*)d_in[20];
    const float* mask11 = (const float*)d_in[21];
    const float* mask13 = (const float*)d_in[22];
    const float* mask15 = (const float*)d_in[23];

    float *pm, *pA, *pB, *pC;
    cudaGetSymbolAddress((void**)&pm, g_mem);
    cudaGetSymbolAddress((void**)&pA, g_A);
    cudaGetSymbolAddress((void**)&pB, g_B);
    cudaGetSymbolAddress((void**)&pC, g_C);

    float* m0  = pm + OFF_M0;
    float* m1  = pm + OFF_M1;
    float* m2  = pm + OFF_M2;
    float* m3  = pm + OFF_M3;
    float* m4  = pm + OFF_M4;
    float* m5  = pm + OFF_M5;
    float* m6  = pm + OFF_M6;
    float* m7  = pm + OFF_M7;
    float* m8  = pm + OFF_M8;
    float* m9  = pm + OFF_M9;
    float* m10 = pm + OFF_M10;

    zero_kernel<<<(MEM_TOTAL + 255) / 256, 256>>>(pm, (int)MEM_TOTAL);
    zero_kernel<<<2, 256>>>((float*)d_out, out_size);

    for (int t = 0; t < TSTEPS; ++t) {
        // pre-process (32x32, 64ch)
        conv_fused<32, 3, 64, 1, 3, 4, 4, 4, 1, 256, 0><<<512, 256>>>(
            x, w_pre0, nullptr, mask2, nullptr, nullptr, m0, pA, thr, leak, 0);
        conv_fused<32, 64, 64, 1, 4, 4, 4, 4, 1, 256, 0><<<512, 256>>>(
            pA, w_pre1, nullptr, mask5, nullptr, nullptr, m1, pB, thr, leak, 1);
        conv_fused<32, 64, 64, 1, 4, 4, 4, 4, 1, 256, 0><<<512, 256>>>(
            pB, w_pre2, nullptr, nullptr, nullptr, nullptr, m2, pA, thr, leak, 2);
        avgpool2_kernel<<<(B * 64 * 16 * 16 + 255) / 256, 256>>>(pA, pB, 64, 16, 16);

        // layer1 (identity shortcut)
        conv_fused<16, 64, 64, 1, 8, 4, 4, 16, 1, 256, 0><<<128, 256>>>(
            pB, w1a, nullptr, mask9, nullptr, nullptr, m3, pC, thr, leak, 3);
        conv_fused<16, 64, 64, 1, 8, 4, 4, 16, 1, 256, 0><<<128, 256>>>(
            pC, w1b, pB, nullptr, nullptr, nullptr, m4, pA, thr, leak, 4);

        // layer2 (fused 1x1-s2 shortcut in conv-b)
        conv_fused<16, 64, 128, 2, 4, 2, 4, 16, 2, 256, 0><<<128, 256>>>(
            pA, w2a, nullptr, mask11, nullptr, nullptr, m5, pB, thr, leak, 5);
        conv_fused<8, 128, 128, 1, 8, 4, 4, 16, 2, 128, 64><<<128, 128>>>(
            pB, w2b, nullptr, nullptr, pA, w2i, m6, pC, thr, leak, 6);

        // layer3
        conv_fused<8, 128, 256, 2, 8, 2, 2, 16, 2, 128, 0><<<256, 128>>>(
            pC, w3a, nullptr, mask13, nullptr, nullptr, m7, pA, thr, leak, 7);
        conv_fused<4, 256, 256, 1, 8, 2, 4, 32, 2, 128, 128><<<128, 128>>>(
            pA, w3b, nullptr, nullptr, pC, w3i, m8, pB, thr, leak, 8);

        // layer4
        conv_fused<4, 256, 512, 2, 8, 2, 2, 32, 4, 128, 0><<<128, 128>>>(
            pB, w4a, nullptr, mask15, nullptr, nullptr, m9, pC, thr, leak, 9);
        conv_fused<2, 512, 512, 1, 16, 2, 2, 32, 4, 128, 256><<<128, 128>>>(
            pC, w4b, nullptr, nullptr, pB, w4i, m10, pA, thr, leak, 10);

        // classifier accumulation
        fc_acc<<<40, 256>>>(pA, w_fc, (float*)d_out);
    }
}